// round 15
// baseline (speedup 1.0000x reference)
#include <cuda_runtime.h>
#include <cuda_fp16.h>
#include <math.h>
#include <stdint.h>

// ---------------- problem constants ----------------
#define BB   4
#define SS   1024
#define DD   1024
#define HH   16
#define HDIM 64
#define LL   2
#define DFF  4096
#define MM   (BB*SS)
#define QKVN 3072

// ---------------- static device scratch ----------------
__device__ __align__(256) __half g_tmph[(size_t)MM*DD];
__device__ __align__(256) __half g_hsh [(size_t)MM*DD];
__device__ __align__(256) __half g_qkv [(size_t)MM*QKVN];
__device__ __align__(256) __half g_ctx [(size_t)MM*DD];
__device__ __align__(256) __half g_attnh[(size_t)MM*DD];
__device__ __align__(256) __half g_ffn1[(size_t)MM*DFF];

__device__ __align__(256) __half g_wqkv[(size_t)DD*QKVN];
__device__ __align__(256) float  g_bqkv[QKVN];
__device__ __align__(256) __half g_wo  [(size_t)DD*DD];
__device__ __align__(256) __half g_w1  [(size_t)LL*DD*DFF];
__device__ __align__(256) __half g_w2  [(size_t)LL*DFF*DD];

// ---------------- asm helpers ----------------
__device__ __forceinline__ uint32_t smem_u32(const void* p) {
    uint32_t a;
    asm("{ .reg .u64 t; cvta.to.shared.u64 t, %1; cvt.u32.u64 %0, t; }"
        : "=r"(a) : "l"(p));
    return a;
}
#define CP16(dst, src) asm volatile("cp.async.cg.shared.global [%0], [%1], 16;" :: "r"(dst), "l"(src) : "memory")
#define CPCOMMIT()     asm volatile("cp.async.commit_group;" ::: "memory")
#define CPWAIT1()      asm volatile("cp.async.wait_group 1;" ::: "memory")
#define CPWAIT0()      asm volatile("cp.async.wait_group 0;" ::: "memory")

__device__ __forceinline__ void ldsm4(uint32_t* r, uint32_t a) {
    asm volatile("ldmatrix.sync.aligned.m8n8.x4.shared.b16 {%0,%1,%2,%3}, [%4];"
        : "=r"(r[0]), "=r"(r[1]), "=r"(r[2]), "=r"(r[3]) : "r"(a));
}
__device__ __forceinline__ void ldsm4t(uint32_t* r, uint32_t a) {
    asm volatile("ldmatrix.sync.aligned.m8n8.x4.trans.shared.b16 {%0,%1,%2,%3}, [%4];"
        : "=r"(r[0]), "=r"(r[1]), "=r"(r[2]), "=r"(r[3]) : "r"(a));
}
__device__ __forceinline__ void mma_f16(float* c, const uint32_t* a, const uint32_t* b) {
    asm volatile(
        "mma.sync.aligned.m16n8k16.row.col.f32.f16.f16.f32 "
        "{%0,%1,%2,%3}, {%4,%5,%6,%7}, {%8,%9}, {%0,%1,%2,%3};"
        : "+f"(c[0]), "+f"(c[1]), "+f"(c[2]), "+f"(c[3])
        : "r"(a[0]), "r"(a[1]), "r"(a[2]), "r"(a[3]), "r"(b[0]), "r"(b[1]));
}
__device__ __forceinline__ float gelu_exact(float x) {
    return 0.5f * x * (1.0f + erff(x * 0.70710678118654752440f));
}
__device__ __forceinline__ uint32_t pack2h(float v0, float v1) {
    __half2 p = __floats2half2_rn(v0, v1);
    return *reinterpret_cast<uint32_t*>(&p);
}

// ================== convert: fp32 -> fp16 (2x float4 per thread) ============
__global__ __launch_bounds__(256) void cvt_fp16(
    const float* __restrict__ src, __half* __restrict__ dst)
{
    int idx = (blockIdx.x * 256 + threadIdx.x) * 2;
    float4 v0 = ((const float4*)src)[idx];
    float4 v1 = ((const float4*)src)[idx + 1];
    uint4 o;
    o.x = pack2h(v0.x, v0.y);
    o.y = pack2h(v0.z, v0.w);
    o.z = pack2h(v1.x, v1.y);
    o.w = pack2h(v1.z, v1.w);
    ((uint4*)dst)[blockIdx.x * 256 + threadIdx.x] = o;
}

// ================== pack QKV weights: [D,3D] fp16 ==================
__global__ __launch_bounds__(256) void pack_qkv_w(
    const float* __restrict__ q, const float* __restrict__ k,
    const float* __restrict__ v, __half* __restrict__ dst)
{
    int i4 = blockIdx.x * 256 + threadIdx.x;
    int row = i4 / (QKVN / 4);
    int c   = (i4 % (QKVN / 4)) * 4;
    const float* src = (c < 1024) ? q + (size_t)row * 1024 + c
                     : (c < 2048) ? k + (size_t)row * 1024 + (c - 1024)
                                  : v + (size_t)row * 1024 + (c - 2048);
    float4 vv = *(const float4*)src;
    ((uint32_t*)dst)[i4 * 2]     = pack2h(vv.x, vv.y);
    ((uint32_t*)dst)[i4 * 2 + 1] = pack2h(vv.z, vv.w);
}
__global__ __launch_bounds__(256) void pack_qkv_b(
    const float* __restrict__ q, const float* __restrict__ k,
    const float* __restrict__ v, float* __restrict__ o)
{
    int idx = blockIdx.x * 256 + threadIdx.x;
    o[idx] = (idx < 1024) ? q[idx] : (idx < 2048) ? k[idx - 1024] : v[idx - 2048];
}

// ================== GEMM: C = A*B + bias, fp16 via mma.sync ==================
// 128x128 tile, 256 threads, 2(m)x4(n) warps, BK=64, 2-stage, occ 2.
// stage: A[128][144B] = 18432 + B[64][272B] = 17408 -> 35840 B
// Epilogue: staged through smem, 16B/thread coalesced stores.
#define GM_STAGE 35840
template<int ACT>
__global__ __launch_bounds__(256, 2) void gemm_fp16(
    const __half* __restrict__ Aa, const __half* __restrict__ Bw,
    const float* __restrict__ bias, __half* __restrict__ Chf,
    int M, int N, int K)
{
    extern __shared__ char sm[];
    const uint32_t smb = smem_u32(sm);
    const int tid = threadIdx.x, lane = tid & 31, wid = tid >> 5;
    const int warp_m = wid >> 2, warp_n = wid & 3;
    const int bm = blockIdx.y * 128, bn = blockIdx.x * 128;

    float c[4][4][4];
    #pragma unroll
    for (int i = 0; i < 4; i++)
        #pragma unroll
        for (int j = 0; j < 4; j++)
            #pragma unroll
            for (int q = 0; q < 4; q++) c[i][j][q] = 0.f;

    const int rowA  = (lane & 7) + ((lane >> 3) & 1) * 8;
    const int kselA = (lane >> 4) * 8;
    const int kB    = (lane & 7) + ((lane >> 3) & 1) * 8;
    const int nB    = ((lane >> 4) & 1) * 8;

    auto load_stage = [&](int s, int k0) {
        uint32_t base = smb + s * GM_STAGE;
        #pragma unroll
        for (int i = 0; i < 4; i++) {
            int cidx = tid + i * 256;
            int row = cidx >> 3, kc = (cidx & 7) << 3;
            size_t g = (size_t)(bm + row) * K + k0 + kc;
            CP16(base + row * 144 + kc * 2, Aa + g);
        }
        #pragma unroll
        for (int i = 0; i < 4; i++) {
            int cidx = tid + i * 256;
            int k = cidx >> 4, nc = (cidx & 15) << 3;
            size_t g = (size_t)(k0 + k) * N + bn + nc;
            CP16(base + 18432 + k * 272 + nc * 2, Bw + g);
        }
        CPCOMMIT();
    };

    auto compute = [&](int s) {
        uint32_t bA = smb + s * GM_STAGE;
        uint32_t bB = bA + 18432;
        #pragma unroll
        for (int ks = 0; ks < 4; ks++) {
            uint32_t bf[4][2];
            #pragma unroll
            for (int ntp = 0; ntp < 2; ntp++) {
                uint32_t off = (uint32_t)((ks * 16 + kB) * 272 +
                                          (warp_n * 32 + ntp * 16 + nB) * 2);
                uint32_t r[4];
                ldsm4t(r, bB + off);
                bf[2*ntp][0] = r[0]; bf[2*ntp][1] = r[1];
                bf[2*ntp+1][0] = r[2]; bf[2*ntp+1][1] = r[3];
            }
            #pragma unroll
            for (int mt = 0; mt < 4; mt++) {
                uint32_t off = (uint32_t)((warp_m * 64 + mt * 16 + rowA) * 144 +
                                          (ks * 16 + kselA) * 2);
                uint32_t af[4];
                ldsm4(af, bA + off);
                #pragma unroll
                for (int nt = 0; nt < 4; nt++)
                    mma_f16(c[mt][nt], af, bf[nt]);
            }
        }
    };

    const int nt_k = K >> 6;
    load_stage(0, 0);
    for (int t = 0; t < nt_k; t++) {
        if (t + 1 < nt_k) { load_stage((t + 1) & 1, (t + 1) << 6); CPWAIT1(); }
        else              { CPWAIT0(); }
        __syncthreads();
        compute(t & 1);
        __syncthreads();
    }

    // ---- epilogue: bias (+GELU), stage to smem, coalesced store ----
    const int g = lane >> 2, tig = lane & 3;
    #pragma unroll
    for (int mt = 0; mt < 4; mt++) {
        #pragma unroll
        for (int nt = 0; nt < 4; nt++) {
            int col_l = warp_n * 32 + nt * 8 + tig * 2;
            float b0 = bias[bn + col_l], b1 = bias[bn + col_l + 1];
            #pragma unroll
            for (int half = 0; half < 2; half++) {
                int row_l = warp_m * 64 + mt * 16 + g + half * 8;
                float v0 = c[mt][nt][half * 2 + 0] + b0;
                float v1 = c[mt][nt][half * 2 + 1] + b1;
                if (ACT) { v0 = gelu_exact(v0); v1 = gelu_exact(v1); }
                *(uint32_t*)(sm + row_l * 272 + col_l * 2) = pack2h(v0, v1);
            }
        }
    }
    __syncthreads();
    #pragma unroll
    for (int i = 0; i < 8; i++) {
        int idx = tid + i * 256;
        int r = idx >> 4, u = idx & 15;
        uint4 val = *(uint4*)(sm + r * 272 + u * 16);
        *(uint4*)&Chf[(size_t)(bm + r) * N + bn + u * 8] = val;
    }
}

// ================== fused flash attention (fp16, 2-stage KV, occ 2) =========
// smem: Q 18432 | 2 stages x [K 18432 | V 18432] | mask 4096
// Epilogue: ctx tile staged through the (dead) Q region, coalesced stores.
#define FA_Q    0
#define FA_K(s) (18432 + (s) * 36864)
#define FA_MASK 92160
#define FA_SMEM 96256

__global__ __launch_bounds__(256, 2) void flash_attn(
    const __half* __restrict__ qkv,
    const float* __restrict__ mask, const float* __restrict__ head_mask,
    int layer, __half* __restrict__ Cc)
{
    extern __shared__ char sm[];
    const uint32_t smb = smem_u32(sm);
    const float* sm_mask = (const float*)(sm + FA_MASK);
    const int tid = threadIdx.x, lane = tid & 31, wid = tid >> 5;
    const int bh = blockIdx.y, b = bh >> 4, h = bh & 15;
    const int si = blockIdx.x * 128;
    const float hm = head_mask[layer * HH + h];

    #pragma unroll
    for (int i = 0; i < 4; i++) {
        int idx = tid + i * 256;
        int r = idx >> 3, cc = (idx & 7) << 3;
        size_t gq = (size_t)(b * SS + si + r) * QKVN + h * 64 + cc;
        CP16(smb + FA_Q + r * 144 + cc * 2, qkv + gq);
    }
    CP16(smb + FA_MASK + tid * 16, mask + b * SS + tid * 4);

    auto load_kv = [&](int s, int t0) {
        uint32_t base = smb + FA_K(s);
        #pragma unroll
        for (int i = 0; i < 4; i++) {
            int idx = tid + i * 256;
            int r = idx >> 3, cc = (idx & 7) << 3;
            size_t gk = (size_t)(b * SS + t0 + r) * QKVN + 1024 + h * 64 + cc;
            size_t gv = (size_t)(b * SS + t0 + r) * QKVN + 2048 + h * 64 + cc;
            CP16(base + r * 144 + cc * 2, qkv + gk);
            CP16(base + 18432 + r * 144 + cc * 2, qkv + gv);
        }
        CPCOMMIT();
    };
    load_kv(0, 0);

    const int rowA  = (lane & 7) + ((lane >> 3) & 1) * 8;
    const int kselA = (lane >> 4) * 8;
    const int rowK  = (lane & 7) + ((lane >> 4) & 1) * 8;
    const int dselK = ((lane >> 3) & 1) * 8;
    const int kB    = (lane & 7) + ((lane >> 3) & 1) * 8;
    const int nB    = ((lane >> 4) & 1) * 8;
    const int g = lane >> 2, tig = lane & 3;

    float m_prev0 = -INFINITY, m_prev1 = -INFINITY;
    float l0 = 0.f, l1 = 0.f;
    float acc[8][4];
    #pragma unroll
    for (int i = 0; i < 8; i++)
        #pragma unroll
        for (int q = 0; q < 4; q++) acc[i][q] = 0.f;

    const float scale = 0.125f;

    for (int kc = 0; kc < SS / 128; kc++) {
        const int s = kc & 1;
        if (kc + 1 < SS / 128) { load_kv((kc + 1) & 1, (kc + 1) * 128); CPWAIT1(); }
        else                   { CPWAIT0(); }
        __syncthreads();

        float c[16][4];
        #pragma unroll
        for (int i = 0; i < 16; i++)
            #pragma unroll
            for (int q = 0; q < 4; q++) c[i][q] = 0.f;

        uint32_t kb = smb + FA_K(s);
        #pragma unroll
        for (int ks = 0; ks < 4; ks++) {
            uint32_t af[4];
            uint32_t offa = (uint32_t)((wid * 16 + rowA) * 144 + (ks * 16 + kselA) * 2);
            ldsm4(af, smb + FA_Q + offa);
            #pragma unroll
            for (int ntp = 0; ntp < 8; ntp++) {
                uint32_t offb = (uint32_t)((ntp * 16 + rowK) * 144 + (ks * 16 + dselK) * 2);
                uint32_t r4[4];
                ldsm4(r4, kb + offb);
                uint32_t be[2] = { r4[0], r4[1] }, bo[2] = { r4[2], r4[3] };
                mma_f16(c[2*ntp],   af, be);
                mma_f16(c[2*ntp+1], af, bo);
            }
        }

        float mx0 = -INFINITY, mx1 = -INFINITY;
        #pragma unroll
        for (int nt = 0; nt < 16; nt++) {
            int col = kc * 128 + nt * 8 + tig * 2;
            float mk0 = sm_mask[col], mk1 = sm_mask[col + 1];
            c[nt][0] = c[nt][0] * scale + mk0;
            c[nt][1] = c[nt][1] * scale + mk1;
            c[nt][2] = c[nt][2] * scale + mk0;
            c[nt][3] = c[nt][3] * scale + mk1;
            mx0 = fmaxf(mx0, fmaxf(c[nt][0], c[nt][1]));
            mx1 = fmaxf(mx1, fmaxf(c[nt][2], c[nt][3]));
        }
        mx0 = fmaxf(mx0, __shfl_xor_sync(0xffffffffu, mx0, 1));
        mx0 = fmaxf(mx0, __shfl_xor_sync(0xffffffffu, mx0, 2));
        mx1 = fmaxf(mx1, __shfl_xor_sync(0xffffffffu, mx1, 1));
        mx1 = fmaxf(mx1, __shfl_xor_sync(0xffffffffu, mx1, 2));

        float mn0 = fmaxf(m_prev0, mx0), mn1 = fmaxf(m_prev1, mx1);
        float al0 = __expf(m_prev0 - mn0), al1 = __expf(m_prev1 - mn1);
        m_prev0 = mn0; m_prev1 = mn1;

        float s0 = 0.f, s1 = 0.f;
        #pragma unroll
        for (int nt = 0; nt < 16; nt++) {
            c[nt][0] = __expf(c[nt][0] - mn0);
            c[nt][1] = __expf(c[nt][1] - mn0);
            c[nt][2] = __expf(c[nt][2] - mn1);
            c[nt][3] = __expf(c[nt][3] - mn1);
            s0 += c[nt][0] + c[nt][1];
            s1 += c[nt][2] + c[nt][3];
        }
        s0 += __shfl_xor_sync(0xffffffffu, s0, 1);
        s0 += __shfl_xor_sync(0xffffffffu, s0, 2);
        s1 += __shfl_xor_sync(0xffffffffu, s1, 1);
        s1 += __shfl_xor_sync(0xffffffffu, s1, 2);
        l0 = l0 * al0 + s0;
        l1 = l1 * al1 + s1;

        #pragma unroll
        for (int d = 0; d < 8; d++) {
            acc[d][0] *= al0; acc[d][1] *= al0;
            acc[d][2] *= al1; acc[d][3] *= al1;
        }

        uint32_t vb = smb + FA_K(s) + 18432;
        #pragma unroll
        for (int ks2 = 0; ks2 < 8; ks2++) {
            uint32_t pa[4];
            pa[0] = pack2h(c[2*ks2][0],   c[2*ks2][1]);
            pa[1] = pack2h(c[2*ks2][2],   c[2*ks2][3]);
            pa[2] = pack2h(c[2*ks2+1][0], c[2*ks2+1][1]);
            pa[3] = pack2h(c[2*ks2+1][2], c[2*ks2+1][3]);
            #pragma unroll
            for (int ntp2 = 0; ntp2 < 4; ntp2++) {
                uint32_t offv = (uint32_t)((ks2 * 16 + kB) * 144 + (ntp2 * 16 + nB) * 2);
                uint32_t r4[4];
                ldsm4t(r4, vb + offv);
                uint32_t ve[2] = { r4[0], r4[1] }, vo[2] = { r4[2], r4[3] };
                mma_f16(acc[2*ntp2],   pa, ve);
                mma_f16(acc[2*ntp2+1], pa, vo);
            }
        }
        __syncthreads();
    }

    // ---- epilogue: stage ctx tile in (dead) Q region, coalesced store ----
    const float inv0 = hm / l0, inv1 = hm / l1;
    #pragma unroll
    for (int d = 0; d < 8; d++) {
        int col = d * 8 + tig * 2;
        int r0 = wid * 16 + g, r1 = r0 + 8;
        *(uint32_t*)(sm + r0 * 144 + col * 2) = pack2h(acc[d][0] * inv0, acc[d][1] * inv0);
        *(uint32_t*)(sm + r1 * 144 + col * 2) = pack2h(acc[d][2] * inv1, acc[d][3] * inv1);
    }
    __syncthreads();
    #pragma unroll
    for (int i = 0; i < 4; i++) {
        int idx = tid + i * 256;            // 0..1023
        int r = idx >> 3, u = idx & 7;      // row, 16B unit (64 cols = 8 units)
        uint4 val = *(uint4*)(sm + r * 144 + u * 16);
        *(uint4*)&Cc[(size_t)(b * SS + si + r) * DD + h * 64 + u * 8] = val;
    }
}

// ================== residual + LayerNorm ==================
template<int XHALF, int WOUT, int WOH>
__global__ __launch_bounds__(256) void ln_residual(
    const float* __restrict__ xf, const __half* __restrict__ xh,
    const __half* __restrict__ y,
    const float* __restrict__ g, const float* __restrict__ b,
    float* __restrict__ out, __half* __restrict__ oh)
{
    const int row = blockIdx.x;
    const int tid = threadIdx.x;

    float4 xv;
    if (XHALF) {
        uint2 xu = ((const uint2*)(xh + (size_t)row * DD))[tid];
        __half2 x01 = *reinterpret_cast<__half2*>(&xu.x);
        __half2 x23 = *reinterpret_cast<__half2*>(&xu.y);
        float2 f01 = __half22float2(x01);
        float2 f23 = __half22float2(x23);
        xv = make_float4(f01.x, f01.y, f23.x, f23.y);
    } else {
        xv = ((const float4*)(xf + (size_t)row * DD))[tid];
    }
    uint2 yu = ((const uint2*)(y + (size_t)row * DD))[tid];
    __half2 y01 = *reinterpret_cast<__half2*>(&yu.x);
    __half2 y23 = *reinterpret_cast<__half2*>(&yu.y);
    float2 yf01 = __half22float2(y01);
    float2 yf23 = __half22float2(y23);
    float4 s4 = make_float4(xv.x + yf01.x, xv.y + yf01.y,
                            xv.z + yf23.x, xv.w + yf23.y);

    float s  = s4.x + s4.y + s4.z + s4.w;
    float ss = s4.x * s4.x + s4.y * s4.y + s4.z * s4.z + s4.w * s4.w;

    const int lane = tid & 31, warp = tid >> 5;
    #pragma unroll
    for (int off = 16; off > 0; off >>= 1) {
        s  += __shfl_xor_sync(0xffffffffu, s, off);
        ss += __shfl_xor_sync(0xffffffffu, ss, off);
    }
    __shared__ float ws[8], wss[8];
    if (lane == 0) { ws[warp] = s; wss[warp] = ss; }
    __syncthreads();
    if (warp == 0) {
        float a  = (lane < 8) ? ws[lane]  : 0.f;
        float aa = (lane < 8) ? wss[lane] : 0.f;
        #pragma unroll
        for (int off = 4; off > 0; off >>= 1) {
            a  += __shfl_xor_sync(0xffffffffu, a, off);
            aa += __shfl_xor_sync(0xffffffffu, aa, off);
        }
        if (lane == 0) { ws[0] = a; wss[0] = aa; }
    }
    __syncthreads();
    const float mean = ws[0] * (1.0f / DD);
    const float var  = wss[0] * (1.0f / DD) - mean * mean;
    const float inv  = rsqrtf(var + 1e-12f);

    const float4 gv = ((const float4*)g)[tid];
    const float4 bv = ((const float4*)b)[tid];
    float4 o;
    o.x = (s4.x - mean) * inv * gv.x + bv.x;
    o.y = (s4.y - mean) * inv * gv.y + bv.y;
    o.z = (s4.z - mean) * inv * gv.z + bv.z;
    o.w = (s4.w - mean) * inv * gv.w + bv.w;
    if (WOUT)
        ((float4*)(out + (size_t)row * DD))[tid] = o;
    if (WOH) {
        uint32_t* hp = (uint32_t*)(oh + (size_t)row * DD);
        hp[tid * 2]     = pack2h(o.x, o.y);
        hp[tid * 2 + 1] = pack2h(o.z, o.w);
    }
}

// ================== host orchestration ==================
extern "C" void kernel_launch(void* const* d_in, const int* in_sizes, int n_in,
                              void* d_out, int out_size)
{
    const float* hidden = (const float*)d_in[0];
    const float* amask  = (const float*)d_in[1];
    const float* hmask  = (const float*)d_in[2];
    const float* q_w    = (const float*)d_in[3];
    const float* q_b    = (const float*)d_in[4];
    const float* k_w    = (const float*)d_in[5];
    const float* k_b    = (const float*)d_in[6];
    const float* v_w    = (const float*)d_in[7];
    const float* v_b    = (const float*)d_in[8];
    const float* o_w    = (const float*)d_in[9];
    const float* o_b    = (const float*)d_in[10];
    const float* aln_g  = (const float*)d_in[11];
    const float* aln_b  = (const float*)d_in[12];
    const float* w1     = (const float*)d_in[13];
    const float* b1     = (const float*)d_in[14];
    const float* w2     = (const float*)d_in[15];
    const float* b2     = (const float*)d_in[16];
    const float* fln_g  = (const float*)d_in[17];
    const float* fln_b  = (const float*)d_in[18];
    float* out = (float*)d_out;

    float *bqkvb;
    __half *tmph, *hsh, *qkvb, *ctxb, *attnh, *ffn1b;
    __half *wqkvb, *wob, *w1b, *w2b;
    cudaGetSymbolAddress((void**)&bqkvb, g_bqkv);
    cudaGetSymbolAddress((void**)&tmph,  g_tmph);
    cudaGetSymbolAddress((void**)&hsh,   g_hsh);
    cudaGetSymbolAddress((void**)&qkvb,  g_qkv);
    cudaGetSymbolAddress((void**)&ctxb,  g_ctx);
    cudaGetSymbolAddress((void**)&attnh, g_attnh);
    cudaGetSymbolAddress((void**)&ffn1b, g_ffn1);
    cudaGetSymbolAddress((void**)&wqkvb, g_wqkv);
    cudaGetSymbolAddress((void**)&wob,   g_wo);
    cudaGetSymbolAddress((void**)&w1b,   g_w1);
    cudaGetSymbolAddress((void**)&w2b,   g_w2);

    cudaFuncSetAttribute(gemm_fp16<0>, cudaFuncAttributeMaxDynamicSharedMemorySize, 2*GM_STAGE);
    cudaFuncSetAttribute(gemm_fp16<1>, cudaFuncAttributeMaxDynamicSharedMemorySize, 2*GM_STAGE);
    cudaFuncSetAttribute(flash_attn, cudaFuncAttributeMaxDynamicSharedMemorySize, FA_SMEM);

    pack_qkv_w<<<(DD*QKVN/4)/256, 256>>>(q_w, k_w, v_w, wqkvb);
    pack_qkv_b<<<QKVN/256, 256>>>(q_b, k_b, v_b, bqkvb);
    cvt_fp16<<<(DD*DD)/2048, 256>>>(o_w, wob);
    cvt_fp16<<<(LL*DD*DFF)/2048, 256>>>(w1, w1b);
    cvt_fp16<<<(LL*DFF*DD)/2048, 256>>>(w2, w2b);
    cvt_fp16<<<(MM*DD)/2048, 256>>>(hidden, hsh);

    const dim3 g1(DD/128, MM/128);
    const dim3 g4(DFF/128, MM/128);
    const dim3 gqkv(QKVN/128, MM/128);
    const dim3 fa_grid(SS/128, BB*HH);

    for (int l = 0; l < LL; l++) {
        gemm_fp16<0><<<gqkv, 256, 2*GM_STAGE>>>(hsh, wqkvb, bqkvb,
            qkvb, MM, QKVN, DD);

        flash_attn<<<fa_grid, 256, FA_SMEM>>>(qkvb, amask, hmask, l, ctxb);

        gemm_fp16<0><<<g1, 256, 2*GM_STAGE>>>(ctxb, wob, o_b,
            tmph, MM, DD, DD);

        if (l == 0)
            ln_residual<0,0,1><<<MM, 256>>>(hidden, nullptr, tmph,
                                            aln_g, aln_b, nullptr, attnh);
        else
            ln_residual<1,0,1><<<MM, 256>>>(nullptr, hsh, tmph,
                                            aln_g, aln_b, nullptr, attnh);

        gemm_fp16<1><<<g4, 256, 2*GM_STAGE>>>(attnh,
            w1b + (size_t)l*DD*DFF, b1 + (size_t)l*DFF,
            ffn1b, MM, DFF, DD);
        gemm_fp16<0><<<g1, 256, 2*GM_STAGE>>>(ffn1b,
            w2b + (size_t)l*DFF*DD, b2 + (size_t)l*DD,
            tmph, MM, DD, DFF);

        if (l == LL - 1)
            ln_residual<1,1,0><<<MM, 256>>>(nullptr, attnh, tmph,
                fln_g + (size_t)l*DD, fln_b + (size_t)l*DD, out, hsh);
        else
            ln_residual<1,0,1><<<MM, 256>>>(nullptr, attnh, tmph,
                fln_g + (size_t)l*DD, fln_b + (size_t)l*DD, nullptr, hsh);
    }
}

// round 16
// speedup vs baseline: 1.0193x; 1.0193x over previous
#include <cuda_runtime.h>
#include <cuda_fp16.h>
#include <math.h>
#include <stdint.h>

// ---------------- problem constants ----------------
#define BB   4
#define SS   1024
#define DD   1024
#define HH   16
#define HDIM 64
#define LL   2
#define DFF  4096
#define MM   (BB*SS)
#define QKVN 3072

// ---------------- static device scratch ----------------
__device__ __align__(256) __half g_tmph[(size_t)MM*DD];
__device__ __align__(256) __half g_hsh [(size_t)MM*DD];
__device__ __align__(256) __half g_qkv [(size_t)MM*QKVN];
__device__ __align__(256) __half g_ctx [(size_t)MM*DD];
__device__ __align__(256) __half g_attnh[(size_t)MM*DD];
__device__ __align__(256) __half g_ffn1[(size_t)MM*DFF];

__device__ __align__(256) __half g_wqkv[(size_t)DD*QKVN];
__device__ __align__(256) float  g_bqkv[QKVN];
__device__ __align__(256) __half g_wo  [(size_t)DD*DD];
__device__ __align__(256) __half g_w1  [(size_t)LL*DD*DFF];
__device__ __align__(256) __half g_w2  [(size_t)LL*DFF*DD];

// ---------------- asm helpers ----------------
__device__ __forceinline__ uint32_t smem_u32(const void* p) {
    uint32_t a;
    asm("{ .reg .u64 t; cvta.to.shared.u64 t, %1; cvt.u32.u64 %0, t; }"
        : "=r"(a) : "l"(p));
    return a;
}
#define CP16(dst, src) asm volatile("cp.async.cg.shared.global [%0], [%1], 16;" :: "r"(dst), "l"(src) : "memory")
#define CPCOMMIT()     asm volatile("cp.async.commit_group;" ::: "memory")
#define CPWAIT1()      asm volatile("cp.async.wait_group 1;" ::: "memory")
#define CPWAIT0()      asm volatile("cp.async.wait_group 0;" ::: "memory")

__device__ __forceinline__ void ldsm4(uint32_t* r, uint32_t a) {
    asm volatile("ldmatrix.sync.aligned.m8n8.x4.shared.b16 {%0,%1,%2,%3}, [%4];"
        : "=r"(r[0]), "=r"(r[1]), "=r"(r[2]), "=r"(r[3]) : "r"(a));
}
__device__ __forceinline__ void ldsm4t(uint32_t* r, uint32_t a) {
    asm volatile("ldmatrix.sync.aligned.m8n8.x4.trans.shared.b16 {%0,%1,%2,%3}, [%4];"
        : "=r"(r[0]), "=r"(r[1]), "=r"(r[2]), "=r"(r[3]) : "r"(a));
}
__device__ __forceinline__ void mma_f16(float* c, const uint32_t* a, const uint32_t* b) {
    asm volatile(
        "mma.sync.aligned.m16n8k16.row.col.f32.f16.f16.f32 "
        "{%0,%1,%2,%3}, {%4,%5,%6,%7}, {%8,%9}, {%0,%1,%2,%3};"
        : "+f"(c[0]), "+f"(c[1]), "+f"(c[2]), "+f"(c[3])
        : "r"(a[0]), "r"(a[1]), "r"(a[2]), "r"(a[3]), "r"(b[0]), "r"(b[1]));
}
__device__ __forceinline__ float gelu_exact(float x) {
    return 0.5f * x * (1.0f + erff(x * 0.70710678118654752440f));
}
__device__ __forceinline__ uint32_t pack2h(float v0, float v1) {
    __half2 p = __floats2half2_rn(v0, v1);
    return *reinterpret_cast<uint32_t*>(&p);
}
// packed fp16 exp2 of two args (sm_75+)
__device__ __forceinline__ uint32_t ex2_h2(float a0, float a1) {
    __half2 h = __floats2half2_rn(a0, a1);
    uint32_t in = *reinterpret_cast<uint32_t*>(&h);
    uint32_t out;
    asm("ex2.approx.f16x2 %0, %1;" : "=r"(out) : "r"(in));
    return out;
}

// ================== convert: fp32 -> fp16 (2x float4 per thread) ============
__global__ __launch_bounds__(256) void cvt_fp16(
    const float* __restrict__ src, __half* __restrict__ dst)
{
    int idx = (blockIdx.x * 256 + threadIdx.x) * 2;
    float4 v0 = ((const float4*)src)[idx];
    float4 v1 = ((const float4*)src)[idx + 1];
    uint4 o;
    o.x = pack2h(v0.x, v0.y);
    o.y = pack2h(v0.z, v0.w);
    o.z = pack2h(v1.x, v1.y);
    o.w = pack2h(v1.z, v1.w);
    ((uint4*)dst)[blockIdx.x * 256 + threadIdx.x] = o;
}

// ================== pack QKV weights: [D,3D] fp16 ==================
__global__ __launch_bounds__(256) void pack_qkv_w(
    const float* __restrict__ q, const float* __restrict__ k,
    const float* __restrict__ v, __half* __restrict__ dst)
{
    int i4 = blockIdx.x * 256 + threadIdx.x;
    int row = i4 / (QKVN / 4);
    int c   = (i4 % (QKVN / 4)) * 4;
    const float* src = (c < 1024) ? q + (size_t)row * 1024 + c
                     : (c < 2048) ? k + (size_t)row * 1024 + (c - 1024)
                                  : v + (size_t)row * 1024 + (c - 2048);
    float4 vv = *(const float4*)src;
    ((uint32_t*)dst)[i4 * 2]     = pack2h(vv.x, vv.y);
    ((uint32_t*)dst)[i4 * 2 + 1] = pack2h(vv.z, vv.w);
}
__global__ __launch_bounds__(256) void pack_qkv_b(
    const float* __restrict__ q, const float* __restrict__ k,
    const float* __restrict__ v, float* __restrict__ o)
{
    int idx = blockIdx.x * 256 + threadIdx.x;
    o[idx] = (idx < 1024) ? q[idx] : (idx < 2048) ? k[idx - 1024] : v[idx - 2048];
}

// ================== GEMM: C = A*B + bias, fp16 via mma.sync ==================
// 128x128 tile, 256 threads, 2(m)x4(n) warps, BK=64, 2-stage, occ 2.
// stage: A[128][144B] = 18432 + B[64][272B] = 17408 -> 35840 B
#define GM_STAGE 35840
template<int ACT>
__global__ __launch_bounds__(256, 2) void gemm_fp16(
    const __half* __restrict__ Aa, const __half* __restrict__ Bw,
    const float* __restrict__ bias, __half* __restrict__ Chf,
    int M, int N, int K)
{
    extern __shared__ char sm[];
    const uint32_t smb = smem_u32(sm);
    const int tid = threadIdx.x, lane = tid & 31, wid = tid >> 5;
    const int warp_m = wid >> 2, warp_n = wid & 3;
    const int bm = blockIdx.y * 128, bn = blockIdx.x * 128;

    float c[4][4][4];
    #pragma unroll
    for (int i = 0; i < 4; i++)
        #pragma unroll
        for (int j = 0; j < 4; j++)
            #pragma unroll
            for (int q = 0; q < 4; q++) c[i][j][q] = 0.f;

    const int rowA  = (lane & 7) + ((lane >> 3) & 1) * 8;
    const int kselA = (lane >> 4) * 8;
    const int kB    = (lane & 7) + ((lane >> 3) & 1) * 8;
    const int nB    = ((lane >> 4) & 1) * 8;

    auto load_stage = [&](int s, int k0) {
        uint32_t base = smb + s * GM_STAGE;
        #pragma unroll
        for (int i = 0; i < 4; i++) {
            int cidx = tid + i * 256;
            int row = cidx >> 3, kc = (cidx & 7) << 3;
            size_t g = (size_t)(bm + row) * K + k0 + kc;
            CP16(base + row * 144 + kc * 2, Aa + g);
        }
        #pragma unroll
        for (int i = 0; i < 4; i++) {
            int cidx = tid + i * 256;
            int k = cidx >> 4, nc = (cidx & 15) << 3;
            size_t g = (size_t)(k0 + k) * N + bn + nc;
            CP16(base + 18432 + k * 272 + nc * 2, Bw + g);
        }
        CPCOMMIT();
    };

    auto compute = [&](int s) {
        uint32_t bA = smb + s * GM_STAGE;
        uint32_t bB = bA + 18432;
        #pragma unroll
        for (int ks = 0; ks < 4; ks++) {
            uint32_t bf[4][2];
            #pragma unroll
            for (int ntp = 0; ntp < 2; ntp++) {
                uint32_t off = (uint32_t)((ks * 16 + kB) * 272 +
                                          (warp_n * 32 + ntp * 16 + nB) * 2);
                uint32_t r[4];
                ldsm4t(r, bB + off);
                bf[2*ntp][0] = r[0]; bf[2*ntp][1] = r[1];
                bf[2*ntp+1][0] = r[2]; bf[2*ntp+1][1] = r[3];
            }
            #pragma unroll
            for (int mt = 0; mt < 4; mt++) {
                uint32_t off = (uint32_t)((warp_m * 64 + mt * 16 + rowA) * 144 +
                                          (ks * 16 + kselA) * 2);
                uint32_t af[4];
                ldsm4(af, bA + off);
                #pragma unroll
                for (int nt = 0; nt < 4; nt++)
                    mma_f16(c[mt][nt], af, bf[nt]);
            }
        }
    };

    const int nt_k = K >> 6;
    load_stage(0, 0);
    for (int t = 0; t < nt_k; t++) {
        if (t + 1 < nt_k) { load_stage((t + 1) & 1, (t + 1) << 6); CPWAIT1(); }
        else              { CPWAIT0(); }
        __syncthreads();
        compute(t & 1);
        __syncthreads();
    }

    // ---- epilogue: bias (+GELU), stage to smem, coalesced store ----
    const int g = lane >> 2, tig = lane & 3;
    #pragma unroll
    for (int mt = 0; mt < 4; mt++) {
        #pragma unroll
        for (int nt = 0; nt < 4; nt++) {
            int col_l = warp_n * 32 + nt * 8 + tig * 2;
            float b0 = bias[bn + col_l], b1 = bias[bn + col_l + 1];
            #pragma unroll
            for (int half = 0; half < 2; half++) {
                int row_l = warp_m * 64 + mt * 16 + g + half * 8;
                float v0 = c[mt][nt][half * 2 + 0] + b0;
                float v1 = c[mt][nt][half * 2 + 1] + b1;
                if (ACT) { v0 = gelu_exact(v0); v1 = gelu_exact(v1); }
                *(uint32_t*)(sm + row_l * 272 + col_l * 2) = pack2h(v0, v1);
            }
        }
    }
    __syncthreads();
    #pragma unroll
    for (int i = 0; i < 8; i++) {
        int idx = tid + i * 256;
        int r = idx >> 4, u = idx & 15;
        uint4 val = *(uint4*)(sm + r * 272 + u * 16);
        *(uint4*)&Chf[(size_t)(bm + r) * N + bn + u * 8] = val;
    }
}

// ================== fused flash attention (fp16, 2-stage KV, occ 2) =========
// Softmax in log2 domain with packed ex2.approx.f16x2 (MUFU count halved;
// probs emerge pre-packed as half2 for the PV MMA).
// smem: Q 18432 | 2 stages x [K 18432 | V 18432] | mask 4096
#define FA_Q    0
#define FA_K(s) (18432 + (s) * 36864)
#define FA_MASK 92160
#define FA_SMEM 96256

__global__ __launch_bounds__(256, 2) void flash_attn(
    const __half* __restrict__ qkv,
    const float* __restrict__ mask, const float* __restrict__ head_mask,
    int layer, __half* __restrict__ Cc)
{
    extern __shared__ char sm[];
    const uint32_t smb = smem_u32(sm);
    const float* sm_mask = (const float*)(sm + FA_MASK);
    const int tid = threadIdx.x, lane = tid & 31, wid = tid >> 5;
    const int bh = blockIdx.y, b = bh >> 4, h = bh & 15;
    const int si = blockIdx.x * 128;
    const float hm = head_mask[layer * HH + h];

    #pragma unroll
    for (int i = 0; i < 4; i++) {
        int idx = tid + i * 256;
        int r = idx >> 3, cc = (idx & 7) << 3;
        size_t gq = (size_t)(b * SS + si + r) * QKVN + h * 64 + cc;
        CP16(smb + FA_Q + r * 144 + cc * 2, qkv + gq);
    }
    CP16(smb + FA_MASK + tid * 16, mask + b * SS + tid * 4);

    auto load_kv = [&](int s, int t0) {
        uint32_t base = smb + FA_K(s);
        #pragma unroll
        for (int i = 0; i < 4; i++) {
            int idx = tid + i * 256;
            int r = idx >> 3, cc = (idx & 7) << 3;
            size_t gk = (size_t)(b * SS + t0 + r) * QKVN + 1024 + h * 64 + cc;
            size_t gv = (size_t)(b * SS + t0 + r) * QKVN + 2048 + h * 64 + cc;
            CP16(base + r * 144 + cc * 2, qkv + gk);
            CP16(base + 18432 + r * 144 + cc * 2, qkv + gv);
        }
        CPCOMMIT();
    };
    load_kv(0, 0);

    const int rowA  = (lane & 7) + ((lane >> 3) & 1) * 8;
    const int kselA = (lane >> 4) * 8;
    const int rowK  = (lane & 7) + ((lane >> 4) & 1) * 8;
    const int dselK = ((lane >> 3) & 1) * 8;
    const int kB    = (lane & 7) + ((lane >> 3) & 1) * 8;
    const int nB    = ((lane >> 4) & 1) * 8;
    const int g = lane >> 2, tig = lane & 3;

    float m_prev0 = -INFINITY, m_prev1 = -INFINITY;
    float l0 = 0.f, l1 = 0.f;
    float acc[8][4];
    #pragma unroll
    for (int i = 0; i < 8; i++)
        #pragma unroll
        for (int q = 0; q < 4; q++) acc[i][q] = 0.f;

    const float LOG2E  = 1.4426950408889634f;
    const float scaleL = 0.125f * LOG2E;   // scores scale folded with log2e

    for (int kc = 0; kc < SS / 128; kc++) {
        const int s = kc & 1;
        if (kc + 1 < SS / 128) { load_kv((kc + 1) & 1, (kc + 1) * 128); CPWAIT1(); }
        else                   { CPWAIT0(); }
        __syncthreads();

        float c[16][4];
        #pragma unroll
        for (int i = 0; i < 16; i++)
            #pragma unroll
            for (int q = 0; q < 4; q++) c[i][q] = 0.f;

        uint32_t kb = smb + FA_K(s);
        #pragma unroll
        for (int ks = 0; ks < 4; ks++) {
            uint32_t af[4];
            uint32_t offa = (uint32_t)((wid * 16 + rowA) * 144 + (ks * 16 + kselA) * 2);
            ldsm4(af, smb + FA_Q + offa);
            #pragma unroll
            for (int ntp = 0; ntp < 8; ntp++) {
                uint32_t offb = (uint32_t)((ntp * 16 + rowK) * 144 + (ks * 16 + dselK) * 2);
                uint32_t r4[4];
                ldsm4(r4, kb + offb);
                uint32_t be[2] = { r4[0], r4[1] }, bo[2] = { r4[2], r4[3] };
                mma_f16(c[2*ntp],   af, be);
                mma_f16(c[2*ntp+1], af, bo);
            }
        }

        // scores -> log2 domain: c*scale*log2e + mask*log2e
        float mx0 = -INFINITY, mx1 = -INFINITY;
        #pragma unroll
        for (int nt = 0; nt < 16; nt++) {
            int col = kc * 128 + nt * 8 + tig * 2;
            float mk0 = sm_mask[col] * LOG2E, mk1 = sm_mask[col + 1] * LOG2E;
            c[nt][0] = c[nt][0] * scaleL + mk0;
            c[nt][1] = c[nt][1] * scaleL + mk1;
            c[nt][2] = c[nt][2] * scaleL + mk0;
            c[nt][3] = c[nt][3] * scaleL + mk1;
            mx0 = fmaxf(mx0, fmaxf(c[nt][0], c[nt][1]));
            mx1 = fmaxf(mx1, fmaxf(c[nt][2], c[nt][3]));
        }
        mx0 = fmaxf(mx0, __shfl_xor_sync(0xffffffffu, mx0, 1));
        mx0 = fmaxf(mx0, __shfl_xor_sync(0xffffffffu, mx0, 2));
        mx1 = fmaxf(mx1, __shfl_xor_sync(0xffffffffu, mx1, 1));
        mx1 = fmaxf(mx1, __shfl_xor_sync(0xffffffffu, mx1, 2));

        float mn0 = fmaxf(m_prev0, mx0), mn1 = fmaxf(m_prev1, mx1);
        float al0 = exp2f(m_prev0 - mn0), al1 = exp2f(m_prev1 - mn1);
        m_prev0 = mn0; m_prev1 = mn1;

        // packed fp16 exp2: probs land pre-packed for PV
        uint32_t p[16][2];
        float s0 = 0.f, s1 = 0.f;
        #pragma unroll
        for (int nt = 0; nt < 16; nt++) {
            uint32_t e01 = ex2_h2(c[nt][0] - mn0, c[nt][1] - mn0);
            uint32_t e23 = ex2_h2(c[nt][2] - mn1, c[nt][3] - mn1);
            p[nt][0] = e01; p[nt][1] = e23;
            float2 f01 = __half22float2(*reinterpret_cast<__half2*>(&e01));
            float2 f23 = __half22float2(*reinterpret_cast<__half2*>(&e23));
            s0 += f01.x + f01.y;
            s1 += f23.x + f23.y;
        }
        s0 += __shfl_xor_sync(0xffffffffu, s0, 1);
        s0 += __shfl_xor_sync(0xffffffffu, s0, 2);
        s1 += __shfl_xor_sync(0xffffffffu, s1, 1);
        s1 += __shfl_xor_sync(0xffffffffu, s1, 2);
        l0 = l0 * al0 + s0;
        l1 = l1 * al1 + s1;

        #pragma unroll
        for (int d = 0; d < 8; d++) {
            acc[d][0] *= al0; acc[d][1] *= al0;
            acc[d][2] *= al1; acc[d][3] *= al1;
        }

        uint32_t vb = smb + FA_K(s) + 18432;
        #pragma unroll
        for (int ks2 = 0; ks2 < 8; ks2++) {
            uint32_t pa[4];
            pa[0] = p[2*ks2][0];
            pa[1] = p[2*ks2][1];
            pa[2] = p[2*ks2+1][0];
            pa[3] = p[2*ks2+1][1];
            #pragma unroll
            for (int ntp2 = 0; ntp2 < 4; ntp2++) {
                uint32_t offv = (uint32_t)((ks2 * 16 + kB) * 144 + (ntp2 * 16 + nB) * 2);
                uint32_t r4[4];
                ldsm4t(r4, vb + offv);
                uint32_t ve[2] = { r4[0], r4[1] }, vo[2] = { r4[2], r4[3] };
                mma_f16(acc[2*ntp2],   pa, ve);
                mma_f16(acc[2*ntp2+1], pa, vo);
            }
        }
        __syncthreads();
    }

    // ---- epilogue: stage ctx tile in (dead) Q region, coalesced store ----
    const float inv0 = hm / l0, inv1 = hm / l1;
    #pragma unroll
    for (int d = 0; d < 8; d++) {
        int col = d * 8 + tig * 2;
        int r0 = wid * 16 + g, r1 = r0 + 8;
        *(uint32_t*)(sm + r0 * 144 + col * 2) = pack2h(acc[d][0] * inv0, acc[d][1] * inv0);
        *(uint32_t*)(sm + r1 * 144 + col * 2) = pack2h(acc[d][2] * inv1, acc[d][3] * inv1);
    }
    __syncthreads();
    #pragma unroll
    for (int i = 0; i < 4; i++) {
        int idx = tid + i * 256;
        int r = idx >> 3, u = idx & 7;
        uint4 val = *(uint4*)(sm + r * 144 + u * 16);
        *(uint4*)&Cc[(size_t)(b * SS + si + r) * DD + h * 64 + u * 8] = val;
    }
}

// ================== residual + LayerNorm ==================
template<int XHALF, int WOUT, int WOH>
__global__ __launch_bounds__(256) void ln_residual(
    const float* __restrict__ xf, const __half* __restrict__ xh,
    const __half* __restrict__ y,
    const float* __restrict__ g, const float* __restrict__ b,
    float* __restrict__ out, __half* __restrict__ oh)
{
    const int row = blockIdx.x;
    const int tid = threadIdx.x;

    float4 xv;
    if (XHALF) {
        uint2 xu = ((const uint2*)(xh + (size_t)row * DD))[tid];
        __half2 x01 = *reinterpret_cast<__half2*>(&xu.x);
        __half2 x23 = *reinterpret_cast<__half2*>(&xu.y);
        float2 f01 = __half22float2(x01);
        float2 f23 = __half22float2(x23);
        xv = make_float4(f01.x, f01.y, f23.x, f23.y);
    } else {
        xv = ((const float4*)(xf + (size_t)row * DD))[tid];
    }
    uint2 yu = ((const uint2*)(y + (size_t)row * DD))[tid];
    __half2 y01 = *reinterpret_cast<__half2*>(&yu.x);
    __half2 y23 = *reinterpret_cast<__half2*>(&yu.y);
    float2 yf01 = __half22float2(y01);
    float2 yf23 = __half22float2(y23);
    float4 s4 = make_float4(xv.x + yf01.x, xv.y + yf01.y,
                            xv.z + yf23.x, xv.w + yf23.y);

    float s  = s4.x + s4.y + s4.z + s4.w;
    float ss = s4.x * s4.x + s4.y * s4.y + s4.z * s4.z + s4.w * s4.w;

    const int lane = tid & 31, warp = tid >> 5;
    #pragma unroll
    for (int off = 16; off > 0; off >>= 1) {
        s  += __shfl_xor_sync(0xffffffffu, s, off);
        ss += __shfl_xor_sync(0xffffffffu, ss, off);
    }
    __shared__ float ws[8], wss[8];
    if (lane == 0) { ws[warp] = s; wss[warp] = ss; }
    __syncthreads();
    if (warp == 0) {
        float a  = (lane < 8) ? ws[lane]  : 0.f;
        float aa = (lane < 8) ? wss[lane] : 0.f;
        #pragma unroll
        for (int off = 4; off > 0; off >>= 1) {
            a  += __shfl_xor_sync(0xffffffffu, a, off);
            aa += __shfl_xor_sync(0xffffffffu, aa, off);
        }
        if (lane == 0) { ws[0] = a; wss[0] = aa; }
    }
    __syncthreads();
    const float mean = ws[0] * (1.0f / DD);
    const float var  = wss[0] * (1.0f / DD) - mean * mean;
    const float inv  = rsqrtf(var + 1e-12f);

    const float4 gv = ((const float4*)g)[tid];
    const float4 bv = ((const float4*)b)[tid];
    float4 o;
    o.x = (s4.x - mean) * inv * gv.x + bv.x;
    o.y = (s4.y - mean) * inv * gv.y + bv.y;
    o.z = (s4.z - mean) * inv * gv.z + bv.z;
    o.w = (s4.w - mean) * inv * gv.w + bv.w;
    if (WOUT)
        ((float4*)(out + (size_t)row * DD))[tid] = o;
    if (WOH) {
        uint32_t* hp = (uint32_t*)(oh + (size_t)row * DD);
        hp[tid * 2]     = pack2h(o.x, o.y);
        hp[tid * 2 + 1] = pack2h(o.z, o.w);
    }
}

// ================== host orchestration ==================
extern "C" void kernel_launch(void* const* d_in, const int* in_sizes, int n_in,
                              void* d_out, int out_size)
{
    const float* hidden = (const float*)d_in[0];
    const float* amask  = (const float*)d_in[1];
    const float* hmask  = (const float*)d_in[2];
    const float* q_w    = (const float*)d_in[3];
    const float* q_b    = (const float*)d_in[4];
    const float* k_w    = (const float*)d_in[5];
    const float* k_b    = (const float*)d_in[6];
    const float* v_w    = (const float*)d_in[7];
    const float* v_b    = (const float*)d_in[8];
    const float* o_w    = (const float*)d_in[9];
    const float* o_b    = (const float*)d_in[10];
    const float* aln_g  = (const float*)d_in[11];
    const float* aln_b  = (const float*)d_in[12];
    const float* w1     = (const float*)d_in[13];
    const float* b1     = (const float*)d_in[14];
    const float* w2     = (const float*)d_in[15];
    const float* b2     = (const float*)d_in[16];
    const float* fln_g  = (const float*)d_in[17];
    const float* fln_b  = (const float*)d_in[18];
    float* out = (float*)d_out;

    float *bqkvb;
    __half *tmph, *hsh, *qkvb, *ctxb, *attnh, *ffn1b;
    __half *wqkvb, *wob, *w1b, *w2b;
    cudaGetSymbolAddress((void**)&bqkvb, g_bqkv);
    cudaGetSymbolAddress((void**)&tmph,  g_tmph);
    cudaGetSymbolAddress((void**)&hsh,   g_hsh);
    cudaGetSymbolAddress((void**)&qkvb,  g_qkv);
    cudaGetSymbolAddress((void**)&ctxb,  g_ctx);
    cudaGetSymbolAddress((void**)&attnh, g_attnh);
    cudaGetSymbolAddress((void**)&ffn1b, g_ffn1);
    cudaGetSymbolAddress((void**)&wqkvb, g_wqkv);
    cudaGetSymbolAddress((void**)&wob,   g_wo);
    cudaGetSymbolAddress((void**)&w1b,   g_w1);
    cudaGetSymbolAddress((void**)&w2b,   g_w2);

    cudaFuncSetAttribute(gemm_fp16<0>, cudaFuncAttributeMaxDynamicSharedMemorySize, 2*GM_STAGE);
    cudaFuncSetAttribute(gemm_fp16<1>, cudaFuncAttributeMaxDynamicSharedMemorySize, 2*GM_STAGE);
    cudaFuncSetAttribute(flash_attn, cudaFuncAttributeMaxDynamicSharedMemorySize, FA_SMEM);

    pack_qkv_w<<<(DD*QKVN/4)/256, 256>>>(q_w, k_w, v_w, wqkvb);
    pack_qkv_b<<<QKVN/256, 256>>>(q_b, k_b, v_b, bqkvb);
    cvt_fp16<<<(DD*DD)/2048, 256>>>(o_w, wob);
    cvt_fp16<<<(LL*DD*DFF)/2048, 256>>>(w1, w1b);
    cvt_fp16<<<(LL*DFF*DD)/2048, 256>>>(w2, w2b);
    cvt_fp16<<<(MM*DD)/2048, 256>>>(hidden, hsh);

    const dim3 g1(DD/128, MM/128);
    const dim3 g4(DFF/128, MM/128);
    const dim3 gqkv(QKVN/128, MM/128);
    const dim3 fa_grid(SS/128, BB*HH);

    for (int l = 0; l < LL; l++) {
        gemm_fp16<0><<<gqkv, 256, 2*GM_STAGE>>>(hsh, wqkvb, bqkvb,
            qkvb, MM, QKVN, DD);

        flash_attn<<<fa_grid, 256, FA_SMEM>>>(qkvb, amask, hmask, l, ctxb);

        gemm_fp16<0><<<g1, 256, 2*GM_STAGE>>>(ctxb, wob, o_b,
            tmph, MM, DD, DD);

        if (l == 0)
            ln_residual<0,0,1><<<MM, 256>>>(hidden, nullptr, tmph,
                                            aln_g, aln_b, nullptr, attnh);
        else
            ln_residual<1,0,1><<<MM, 256>>>(nullptr, hsh, tmph,
                                            aln_g, aln_b, nullptr, attnh);

        gemm_fp16<1><<<g4, 256, 2*GM_STAGE>>>(attnh,
            w1b + (size_t)l*DD*DFF, b1 + (size_t)l*DFF,
            ffn1b, MM, DFF, DD);
        gemm_fp16<0><<<g1, 256, 2*GM_STAGE>>>(ffn1b,
            w2b + (size_t)l*DFF*DD, b2 + (size_t)l*DD,
            tmph, MM, DD, DFF);

        if (l == LL - 1)
            ln_residual<1,1,0><<<MM, 256>>>(nullptr, attnh, tmph,
                fln_g + (size_t)l*DD, fln_b + (size_t)l*DD, out, hsh);
        else
            ln_residual<1,0,1><<<MM, 256>>>(nullptr, attnh, tmph,
                fln_g + (size_t)l*DD, fln_b + (size_t)l*DD, nullptr, hsh);
    }
}